// round 16
// baseline (speedup 1.0000x reference)
#include <cuda_runtime.h>
#include <cuda_fp16.h>

#define N_NODES 50000
#define N_EDGES 1600000
#define C_OUT   256
#define SCAN_BLOCKS 196   // ceil(50000/256)
#define W1_N (256*128)
#define W2_N (256*256)
#define W_TOTAL (W1_N + 2*W2_N)

// prep_kernel block ranges
#define SPLIT_BLOCKS 640                   // ceil(W_TOTAL/256)
#define X2H_BLOCKS   6250                  // N_NODES*128/4/256
#define HIST_BLOCKS  782                   // ceil(N_EDGES/8/256)
#define PREP_BLOCKS  (SPLIT_BLOCKS + X2H_BLOCKS + HIST_BLOCKS)

// ---------------- scratch (static device globals; allocation-free) ----------
__device__ int    g_is64;
__device__ int2   g_edge[N_EDGES];     // (src, __float_as_int(ew)) CSR-sorted
__device__ int    g_deg[N_NODES];
__device__ unsigned long long g_state[SCAN_BLOCKS];  // lookback scan state
__device__ int    g_rowoff[N_NODES + 1];
__device__ int    g_cursor[N_NODES];
__device__ __half g_xh[(size_t)N_NODES * 128];       // fp16 copy of input x
__device__ __half g_hf[(size_t)N_NODES * C_OUT];     // fp16 hidden activations
__device__ __half g_agg[(size_t)N_NODES * C_OUT];    // fp16 aggregate
__device__ __half g_WH[W_TOTAL];

__device__ __forceinline__ unsigned h2_as_u32(half2 v) {
    unsigned u;
    memcpy(&u, &v, 4);
    return u;
}

// d(16x8 f32) += A(16x16 f16) * B(16x8 f16)
__device__ __forceinline__ void mma_f16(float c[4], const unsigned a[4],
                                        const unsigned b[2]) {
    asm("mma.sync.aligned.m16n8k16.row.col.f32.f16.f16.f32 "
        "{%0,%1,%2,%3}, {%4,%5,%6,%7}, {%8,%9}, {%0,%1,%2,%3};"
        : "+f"(c[0]), "+f"(c[1]), "+f"(c[2]), "+f"(c[3])
        : "r"(a[0]), "r"(a[1]), "r"(a[2]), "r"(a[3]), "r"(b[0]), "r"(b[1]));
}

// 16-byte async copy gmem->smem; full=false zero-fills (src not read)
__device__ __forceinline__ void cp16(unsigned dst_smem, const void* src, bool full) {
    int sz = full ? 16 : 0;
    asm volatile("cp.async.cg.shared.global [%0], [%1], 16, %2;"
                 :: "r"(dst_smem), "l"(src), "r"(sz));
}
#define CP_COMMIT()  asm volatile("cp.async.commit_group;")
#define CP_WAIT(N)   asm volatile("cp.async.wait_group %0;" :: "n"(N))

// ---------------- fused prep: weight split + detect + state-zero | x2h | hist
__global__ void prep_kernel(const float* __restrict__ W1,
                            const float* __restrict__ W2,
                            const float* __restrict__ W3,
                            const float* __restrict__ x,
                            const int* __restrict__ ei) {
    int blk = blockIdx.x;
    int tid = threadIdx.x;

    if (blk < SPLIT_BLOCKS) {
        if (blk == 0) {
            __shared__ int nz;
            if (tid == 0) nz = 0;
            __syncthreads();
            if (tid < 64 && ei[2 * tid + 1] != 0) nz = 1;
            if (tid < SCAN_BLOCKS) g_state[tid] = 0ULL;   // scan state reset
            __syncthreads();
            if (tid == 0) g_is64 = (nz == 0) ? 1 : 0;
        }
        int i = blk * 256 + tid;
        if (i < W_TOTAL) {
            float v;
            if (i < W1_N)             v = W1[i];
            else if (i < W1_N + W2_N) v = W2[i - W1_N];
            else                      v = W3[i - W1_N - W2_N];
            g_WH[i] = __float2half_rn(v);
        }
    } else if (blk < SPLIT_BLOCKS + X2H_BLOCKS) {
        int i = (blk - SPLIT_BLOCKS) * 256 + tid;   // < 1,600,000 exactly
        float4 v = ((const float4*)x)[i];
        half2 a = __halves2half2(__float2half_rn(v.x), __float2half_rn(v.y));
        half2 b = __halves2half2(__float2half_rn(v.z), __float2half_rn(v.w));
        ((uint2*)g_xh)[i] = make_uint2(h2_as_u32(a), h2_as_u32(b));
    } else {
        __shared__ int is64;
        if (tid == 0) is64 = 1;
        __syncthreads();
        if (tid < 64 && ei[2 * tid + 1] != 0) is64 = 0;
        __syncthreads();
        int e0 = ((blk - SPLIT_BLOCKS - X2H_BLOCKS) * 256 + tid) * 8;
        if (e0 >= N_EDGES) return;
        if (is64) {
            const int4* dw = (const int4*)(ei + 2 * (size_t)N_EDGES);
#pragma unroll
            for (int u = 0; u < 4; u++) {
                int4 v = dw[e0 / 2 + u];
                atomicAdd(&g_deg[v.x], 1);
                atomicAdd(&g_deg[v.z], 1);
            }
        } else {
            const int4* dw = (const int4*)(ei + N_EDGES);
#pragma unroll
            for (int u = 0; u < 2; u++) {
                int4 v = dw[e0 / 4 + u];
                atomicAdd(&g_deg[v.x], 1);
                atomicAdd(&g_deg[v.y], 1);
                atomicAdd(&g_deg[v.z], 1);
                atomicAdd(&g_deg[v.w], 1);
            }
        }
    }
}

// ---------------- single-kernel decoupled-lookback exclusive scan -----------
// Also zeroes g_deg after reading it (readies the buffer for the next graph
// replay, replacing a cudaMemsetAsync node).
__global__ void scan_kernel() {
    const unsigned long long FLAG_A = 2ULL << 62;
    const unsigned long long FLAG_P = 3ULL << 62;
    const unsigned long long VMASK  = 0xFFFFFFFFULL;
    int b = blockIdx.x;
    int tid = threadIdx.x;
    int i = b * 256 + tid;
    int v = 0;
    if (i < N_NODES) {
        v = g_deg[i];
        g_deg[i] = 0;          // reset for next replay
    }

    int lane = tid & 31, wid = tid >> 5;
    int x = v;
#pragma unroll
    for (int o = 1; o < 32; o <<= 1) {
        int t = __shfl_up_sync(~0u, x, o);
        if (lane >= o) x += t;
    }
    __shared__ int ws[8];
    if (lane == 31) ws[wid] = x;
    __syncthreads();
    if (wid == 0 && lane < 8) {
        int w = ws[lane];
#pragma unroll
        for (int o = 1; o < 8; o <<= 1) {
            int t = __shfl_up_sync(0xffu, w, o);
            if (lane >= o) w += t;
        }
        ws[lane] = w;
    }
    __syncthreads();
    int incl = x + (wid > 0 ? ws[wid - 1] : 0);
    int total = ws[7];

    __shared__ int prefix_sh;
    if (tid == 0) {
        if (b == 0) {
            prefix_sh = 0;
            atomicExch(&g_state[0], FLAG_P | (unsigned long long)total);
            g_rowoff[N_NODES] = N_EDGES;
        } else {
            atomicExch(&g_state[b], FLAG_A | (unsigned long long)total);
            long long run = 0;
            int j = b - 1;
            while (true) {
                unsigned long long s;
                do {
                    s = *(volatile unsigned long long*)(g_state + j);
                } while ((s >> 62) < 2);
                run += (long long)(s & VMASK);
                if ((s >> 62) == 3) break;
                j--;
            }
            atomicExch(&g_state[b],
                       FLAG_P | (unsigned long long)(run + total));
            prefix_sh = (int)run;
        }
    }
    __syncthreads();
    int excl = prefix_sh + incl - v;
    if (i < N_NODES) {
        g_rowoff[i] = excl;
        g_cursor[i] = excl;
    }
}

// decode 2 edges/thread, ew = mean(edge_attr,-1), scatter packed into CSR
__global__ void fill_kernel(const int* __restrict__ ei,
                            const float* __restrict__ ea) {
    int e0 = (blockIdx.x * blockDim.x + threadIdx.x) * 2;
    if (e0 >= N_EDGES) return;
    int s0, s1, d0, d1;
    if (g_is64) {
        int4 sv = *(const int4*)(ei + 2 * (size_t)e0);
        int4 dv = *(const int4*)(ei + 2 * (size_t)N_EDGES + 2 * (size_t)e0);
        s0 = sv.x; s1 = sv.z;
        d0 = dv.x; d1 = dv.z;
    } else {
        int2 sv = *(const int2*)(ei + e0);
        int2 dv = *(const int2*)(ei + N_EDGES + e0);
        s0 = sv.x; s1 = sv.y;
        d0 = dv.x; d1 = dv.y;
    }
    const float4* a4 = (const float4*)(ea + (size_t)e0 * 8);
    float4 u0 = a4[0], v0 = a4[1], u1 = a4[2], v1 = a4[3];
    float ew0 = (u0.x + u0.y + u0.z + u0.w + v0.x + v0.y + v0.z + v0.w) * 0.125f;
    float ew1 = (u1.x + u1.y + u1.z + u1.w + v1.x + v1.y + v1.z + v1.w) * 0.125f;
    int p0 = atomicAdd(&g_cursor[d0], 1);
    g_edge[p0] = make_int2(s0, __float_as_int(ew0));
    int p1 = atomicAdd(&g_cursor[d1], 1);
    g_edge[p1] = make_int2(s1, __float_as_int(ew1));
}

// ---------------- gather-aggregate (fp16 rows -> fp16 aggregate) ------------
// out_i = sum_{e: dst=i} in[src_e] * w_e ; fp32 accum, fp16 store.
// Each lane owns 8 channels: one uint4 (16B) per gathered row. 8-way edge
// unroll for MLP (8 outstanding row reads per thread).
template <int C, bool USE_W>
__global__ void gather_kernel(const __half* __restrict__ in,
                              __half* __restrict__ out) {
    constexpr int L = C / 8;        // lanes per node (16 or 32)
    constexpr int G = 256 / L;      // nodes per 256-thread block
    int grp  = threadIdx.x / L;
    int lane = threadIdx.x % L;
    int node = blockIdx.x * G + grp;
    if (node >= N_NODES) return;

    int e0 = g_rowoff[node];
    int e1 = g_rowoff[node + 1];
    const uint4* in4 = (const uint4*)in;   // row stride = C/8 uint4
    float acc[8];
#pragma unroll
    for (int q = 0; q < 8; q++) acc[q] = 0.f;

    int e = e0;
    for (; e + 8 <= e1; e += 8) {
        int2 p[8];
#pragma unroll
        for (int u = 0; u < 8; u++) p[u] = __ldg(&g_edge[e + u]);
        uint4 r[8];
#pragma unroll
        for (int u = 0; u < 8; u++) r[u] = __ldg(&in4[(size_t)p[u].x * L + lane]);
#pragma unroll
        for (int u = 0; u < 8; u++) {
            float w = USE_W ? __int_as_float(p[u].y) : 1.0f;
            half2 h0 = *(half2*)&r[u].x, h1 = *(half2*)&r[u].y;
            half2 h2 = *(half2*)&r[u].z, h3 = *(half2*)&r[u].w;
            float2 f0 = __half22float2(h0), f1 = __half22float2(h1);
            float2 f2 = __half22float2(h2), f3 = __half22float2(h3);
            acc[0] = fmaf(f0.x, w, acc[0]); acc[1] = fmaf(f0.y, w, acc[1]);
            acc[2] = fmaf(f1.x, w, acc[2]); acc[3] = fmaf(f1.y, w, acc[3]);
            acc[4] = fmaf(f2.x, w, acc[4]); acc[5] = fmaf(f2.y, w, acc[5]);
            acc[6] = fmaf(f3.x, w, acc[6]); acc[7] = fmaf(f3.y, w, acc[7]);
        }
    }
    for (; e < e1; e++) {
        int2 p = __ldg(&g_edge[e]);
        float w = USE_W ? __int_as_float(p.y) : 1.0f;
        uint4 r = __ldg(&in4[(size_t)p.x * L + lane]);
        half2 h0 = *(half2*)&r.x, h1 = *(half2*)&r.y;
        half2 h2 = *(half2*)&r.z, h3 = *(half2*)&r.w;
        float2 f0 = __half22float2(h0), f1 = __half22float2(h1);
        float2 f2 = __half22float2(h2), f3 = __half22float2(h3);
        acc[0] = fmaf(f0.x, w, acc[0]); acc[1] = fmaf(f0.y, w, acc[1]);
        acc[2] = fmaf(f1.x, w, acc[2]); acc[3] = fmaf(f1.y, w, acc[3]);
        acc[4] = fmaf(f2.x, w, acc[4]); acc[5] = fmaf(f2.y, w, acc[5]);
        acc[6] = fmaf(f3.x, w, acc[6]); acc[7] = fmaf(f3.y, w, acc[7]);
    }

    half2 hh[4];
#pragma unroll
    for (int q = 0; q < 4; q++)
        hh[q] = __halves2half2(__float2half_rn(acc[2 * q]),
                               __float2half_rn(acc[2 * q + 1]));
    uint4 pH = make_uint4(h2_as_u32(hh[0]), h2_as_u32(hh[1]),
                          h2_as_u32(hh[2]), h2_as_u32(hh[3]));
    *(uint4*)(out + (size_t)node * C + lane * 8) = pH;
}

// ---------------- tensor-core GEMM (fp16, 3-stage cp.async) -----------------
// out[M,256] = A @ W^T + epilogue.  BM=128, BN=64, BK=32, 256 threads =
// 8 warps (4m x 2n), warp tile 32x32 = 2 m-atoms x 4 n-atoms, m16n8k16.
// 3-stage pipeline, ONE __syncthreads per k-tile:
//   wait(stage it ready) -> sync (retires stage it-1's slot) ->
//   load stage it+2 into that slot -> compute stage it.
template <int K, bool BN_RELU, bool OUT_HALF>
__global__ void gemm_tc_kernel(const __half* __restrict__ A,
                               const __half* __restrict__ B,
                               const float* __restrict__ bias,
                               const float* __restrict__ gam,
                               const float* __restrict__ bet,
                               const float* __restrict__ mu,
                               const float* __restrict__ var,
                               void* __restrict__ out_v) {
    constexpr int BM = 128, BN = 64, BK = 32;
    constexpr int PK = 20;  // row pitch in half2: conflict-free frag LDS
    constexpr int NT = K / BK;          // 4 or 8
    constexpr int ST = 3;               // pipeline stages
    __shared__ __align__(16) half2 sA[ST][BM][PK];
    __shared__ __align__(16) half2 sB[ST][BN][PK];

    int m0 = blockIdx.x * BM;
    int n0 = blockIdx.y * BN;
    int tid = threadIdx.x;
    int lane = tid & 31;
    int g = lane >> 2;        // 0..7
    int t = lane & 3;         // 0..3
    int wid = tid >> 5;       // 0..7
    int wm = wid & 3;         // warp m index (0..3)
    int wn = wid >> 2;        // warp n index (0..1)

    int arow = tid >> 1;            // 0..127
    int akq  = (tid & 1) * 16;      // 0 or 16 (halves)
    int brow = tid >> 2;            // 0..63
    int bkq  = (tid & 3) * 8;       // 0,8,16,24 (halves)

    int arow_g   = m0 + arow;
    bool a_ok    = arow_g < N_NODES;
    int arow_cl  = a_ok ? arow_g : 0;       // clamped for address calc

    float acc[2][4][4];
#pragma unroll
    for (int i = 0; i < 2; i++)
#pragma unroll
        for (int j = 0; j < 4; j++)
#pragma unroll
            for (int c = 0; c < 4; c++) acc[i][j][c] = 0.f;

    auto load_tile = [&](int kt, int bf) {
        const __half* ap = A + (size_t)arow_cl * K + kt * BK + akq;
        unsigned dA0 = (unsigned)__cvta_generic_to_shared(&sA[bf][arow][akq / 2]);
        cp16(dA0, ap, a_ok);
        cp16(dA0 + 16, ap + 8, a_ok);
        const __half* bp = B + (size_t)(n0 + brow) * K + kt * BK + bkq;
        unsigned dB = (unsigned)__cvta_generic_to_shared(&sB[bf][brow][bkq / 2]);
        cp16(dB, bp, true);
    };

    // prologue: stages 0 and 1 in flight
    load_tile(0, 0);
    CP_COMMIT();
    load_tile(1, 1);
    CP_COMMIT();

#pragma unroll 1
    for (int it = 0; it < NT; it++) {
        int buf = it % ST;
        if (it + 1 < NT) { CP_WAIT(1); } else { CP_WAIT(0); }
        __syncthreads();                     // stage it-1 fully consumed
        if (it + 2 < NT) {
            load_tile(it + 2, (it + 2) % ST);
            CP_COMMIT();
        }

#pragma unroll
        for (int ko = 0; ko < 2; ko++) {   // two k16 steps per BK=32 tile
            int kb = ko * 8;               // half2 offset
            unsigned ah[2][4], bh[4][2];
#pragma unroll
            for (int i = 0; i < 2; i++) {
                int rm = wm * 32 + i * 16;
                ah[i][0] = h2_as_u32(sA[buf][rm + g][kb + t]);
                ah[i][1] = h2_as_u32(sA[buf][rm + g + 8][kb + t]);
                ah[i][2] = h2_as_u32(sA[buf][rm + g][kb + t + 4]);
                ah[i][3] = h2_as_u32(sA[buf][rm + g + 8][kb + t + 4]);
            }
#pragma unroll
            for (int j = 0; j < 4; j++) {
                int cn = wn * 32 + j * 8;
                bh[j][0] = h2_as_u32(sB[buf][cn + g][kb + t]);
                bh[j][1] = h2_as_u32(sB[buf][cn + g][kb + t + 4]);
            }
#pragma unroll
            for (int i = 0; i < 2; i++)
#pragma unroll
                for (int j = 0; j < 4; j++)
                    mma_f16(acc[i][j], ah[i], bh[j]);
        }
    }

    __syncthreads();   // protect smem before (potential) reuse; cheap, once

    // ---- epilogue: +bias, optional BN(eval)+ReLU ----
#pragma unroll
    for (int j = 0; j < 4; j++) {
        int n = n0 + wn * 32 + j * 8 + 2 * t;
        float b0 = bias[n], b1 = bias[n + 1];
        float s0 = 0.f, s1 = 0.f, t0 = 0.f, t1 = 0.f;
        if (BN_RELU) {
            s0 = gam[n] * rsqrtf(var[n] + 1e-5f);
            t0 = bet[n] - mu[n] * s0;
            s1 = gam[n + 1] * rsqrtf(var[n + 1] + 1e-5f);
            t1 = bet[n + 1] - mu[n + 1] * s1;
        }
#pragma unroll
        for (int i = 0; i < 2; i++) {
            int r0 = m0 + wm * 32 + i * 16 + g;
            int r1 = r0 + 8;
            float z0 = acc[i][j][0] + b0;
            float z1 = acc[i][j][1] + b1;
            float z2 = acc[i][j][2] + b0;
            float z3 = acc[i][j][3] + b1;
            if (BN_RELU) {
                z0 = fmaxf(fmaf(z0, s0, t0), 0.f);
                z1 = fmaxf(fmaf(z1, s1, t1), 0.f);
                z2 = fmaxf(fmaf(z2, s0, t0), 0.f);
                z3 = fmaxf(fmaf(z3, s1, t1), 0.f);
            }
            if (OUT_HALF) {
                __half* oh = (__half*)out_v;
                half2 p0 = __halves2half2(__float2half_rn(z0), __float2half_rn(z1));
                half2 p1 = __halves2half2(__float2half_rn(z2), __float2half_rn(z3));
                if (r0 < N_NODES)
                    *(half2*)(oh + (size_t)r0 * C_OUT + n) = p0;
                if (r1 < N_NODES)
                    *(half2*)(oh + (size_t)r1 * C_OUT + n) = p1;
            } else {
                float* of = (float*)out_v;
                if (r0 < N_NODES)
                    *(float2*)(of + (size_t)r0 * C_OUT + n) = make_float2(z0, z1);
                if (r1 < N_NODES)
                    *(float2*)(of + (size_t)r1 * C_OUT + n) = make_float2(z2, z3);
            }
        }
    }
}

// ---------------- launch ----------------------------------------------------
extern "C" void kernel_launch(void* const* d_in, const int* in_sizes, int n_in,
                              void* d_out, int out_size) {
    const float* x   = (const float*)d_in[0];
    const int*   ei  = (const int*)d_in[1];
    const float* ea  = (const float*)d_in[2];
    const float* W1  = (const float*)d_in[3];
    const float* b1  = (const float*)d_in[4];
    const float* g1  = (const float*)d_in[5];
    const float* be1 = (const float*)d_in[6];
    const float* m1  = (const float*)d_in[7];
    const float* v1  = (const float*)d_in[8];
    const float* W2  = (const float*)d_in[9];
    const float* b2  = (const float*)d_in[10];
    const float* g2  = (const float*)d_in[11];
    const float* be2 = (const float*)d_in[12];
    const float* m2  = (const float*)d_in[13];
    const float* v2  = (const float*)d_in[14];
    const float* W3  = (const float*)d_in[15];
    const float* b3  = (const float*)d_in[16];

    void *p_agg, *p_hf, *p_xh, *p_WH;
    cudaGetSymbolAddress(&p_agg, g_agg);
    cudaGetSymbolAddress(&p_hf, g_hf);
    cudaGetSymbolAddress(&p_xh, g_xh);
    cudaGetSymbolAddress(&p_WH, g_WH);
    __half* agg = (__half*)p_agg;
    __half* hf  = (__half*)p_hf;
    __half* xh  = (__half*)p_xh;
    __half* WH  = (__half*)p_WH;
    const int offW2 = W1_N;
    const int offW3 = W1_N + W2_N;

    // ---- CSR build + conversions (once) ----
    // NOTE: g_deg starts zeroed (static storage) and scan_kernel re-zeroes it
    // each replay; g_state is re-zeroed in prep_kernel block 0.
    prep_kernel<<<PREP_BLOCKS, 256>>>(W1, W2, W3, x, ei);
    scan_kernel<<<SCAN_BLOCKS, 256>>>();
    fill_kernel<<<(N_EDGES / 2 + 255) / 256, 256>>>(ei, ea);

    dim3 ggrid((N_NODES + 127) / 128, 4);  // 391 x 4, BM=128 BN=64

    // ---- layer 1: gather x_fp16 (C=128), GEMM K=128 + BN1 + ReLU -> fp16 h --
    gather_kernel<128, true><<<(N_NODES + 15) / 16, 256>>>(xh, agg);
    gemm_tc_kernel<128, true, true><<<ggrid, 256>>>(agg, WH,
                                                    b1, g1, be1, m1, v1, hf);

    // ---- layer 2: gather h_fp16 (C=256), GEMM K=256 + BN2 + ReLU -> fp16 h --
    gather_kernel<256, true><<<(N_NODES + 7) / 8, 256>>>(hf, agg);
    gemm_tc_kernel<256, true, true><<<ggrid, 256>>>(agg, WH + offW2,
                                                    b2, g2, be2, m2, v2, hf);

    // ---- layer 3: gather h_fp16 (C=256, no weight), GEMM + bias -> fp32 out -
    gather_kernel<256, false><<<(N_NODES + 7) / 8, 256>>>(hf, agg);
    gemm_tc_kernel<256, false, false><<<ggrid, 256>>>(agg, WH + offW3,
                                                      b3, nullptr, nullptr,
                                                      nullptr, nullptr, d_out);
}

// round 17
// speedup vs baseline: 1.0257x; 1.0257x over previous
#include <cuda_runtime.h>
#include <cuda_fp16.h>

#define N_NODES 50000
#define N_EDGES 1600000
#define C_OUT   256
#define SCAN_BLOCKS 196   // ceil(50000/256)
#define W1_N (256*128)
#define W2_N (256*256)
#define W_TOTAL (W1_N + 2*W2_N)

// prep_kernel block ranges
#define SPLIT_BLOCKS 640                   // ceil(W_TOTAL/256)
#define X2H_BLOCKS   6250                  // N_NODES*128/4/256
#define HIST_BLOCKS  782                   // ceil(N_EDGES/8/256)
#define PREP_BLOCKS  (SPLIT_BLOCKS + X2H_BLOCKS + HIST_BLOCKS)

// PDL: consumer waits for producer grid's memory to be visible. No-op if the
// launch carried no PDL attribute.
#define GRID_WAIT() asm volatile("griddepcontrol.wait;" ::: "memory")

// ---------------- scratch (static device globals; allocation-free) ----------
__device__ int    g_is64;
__device__ int2   g_edge[N_EDGES];     // (src, __float_as_int(ew)) CSR-sorted
__device__ int    g_deg[N_NODES];
__device__ unsigned long long g_state[SCAN_BLOCKS];  // lookback scan state
__device__ int    g_rowoff[N_NODES + 1];
__device__ int    g_cursor[N_NODES];
__device__ __half g_xh[(size_t)N_NODES * 128];       // fp16 copy of input x
__device__ __half g_hf[(size_t)N_NODES * C_OUT];     // fp16 hidden activations
__device__ __half g_agg[(size_t)N_NODES * C_OUT];    // fp16 aggregate
__device__ __half g_WH[W_TOTAL];

__device__ __forceinline__ unsigned h2_as_u32(half2 v) {
    unsigned u;
    memcpy(&u, &v, 4);
    return u;
}

// d(16x8 f32) += A(16x16 f16) * B(16x8 f16)
__device__ __forceinline__ void mma_f16(float c[4], const unsigned a[4],
                                        const unsigned b[2]) {
    asm("mma.sync.aligned.m16n8k16.row.col.f32.f16.f16.f32 "
        "{%0,%1,%2,%3}, {%4,%5,%6,%7}, {%8,%9}, {%0,%1,%2,%3};"
        : "+f"(c[0]), "+f"(c[1]), "+f"(c[2]), "+f"(c[3])
        : "r"(a[0]), "r"(a[1]), "r"(a[2]), "r"(a[3]), "r"(b[0]), "r"(b[1]));
}

// 16-byte async copy gmem->smem; full=false zero-fills (src not read)
__device__ __forceinline__ void cp16(unsigned dst_smem, const void* src, bool full) {
    int sz = full ? 16 : 0;
    asm volatile("cp.async.cg.shared.global [%0], [%1], 16, %2;"
                 :: "r"(dst_smem), "l"(src), "r"(sz));
}
#define CP_COMMIT()  asm volatile("cp.async.commit_group;")
#define CP_WAIT(N)   asm volatile("cp.async.wait_group %0;" :: "n"(N))

// ---------------- fused prep: weight split + detect + state-zero | x2h | hist
__global__ void prep_kernel(const float* __restrict__ W1,
                            const float* __restrict__ W2,
                            const float* __restrict__ W3,
                            const float* __restrict__ x,
                            const int* __restrict__ ei) {
    int blk = blockIdx.x;
    int tid = threadIdx.x;

    if (blk < SPLIT_BLOCKS) {
        if (blk == 0) {
            __shared__ int nz;
            if (tid == 0) nz = 0;
            __syncthreads();
            if (tid < 64 && ei[2 * tid + 1] != 0) nz = 1;
            if (tid < SCAN_BLOCKS) g_state[tid] = 0ULL;   // scan state reset
            __syncthreads();
            if (tid == 0) g_is64 = (nz == 0) ? 1 : 0;
        }
        int i = blk * 256 + tid;
        if (i < W_TOTAL) {
            float v;
            if (i < W1_N)             v = W1[i];
            else if (i < W1_N + W2_N) v = W2[i - W1_N];
            else                      v = W3[i - W1_N - W2_N];
            g_WH[i] = __float2half_rn(v);
        }
    } else if (blk < SPLIT_BLOCKS + X2H_BLOCKS) {
        int i = (blk - SPLIT_BLOCKS) * 256 + tid;   // < 1,600,000 exactly
        float4 v = ((const float4*)x)[i];
        half2 a = __halves2half2(__float2half_rn(v.x), __float2half_rn(v.y));
        half2 b = __halves2half2(__float2half_rn(v.z), __float2half_rn(v.w));
        ((uint2*)g_xh)[i] = make_uint2(h2_as_u32(a), h2_as_u32(b));
    } else {
        __shared__ int is64;
        if (tid == 0) is64 = 1;
        __syncthreads();
        if (tid < 64 && ei[2 * tid + 1] != 0) is64 = 0;
        __syncthreads();
        int e0 = ((blk - SPLIT_BLOCKS - X2H_BLOCKS) * 256 + tid) * 8;
        if (e0 >= N_EDGES) return;
        if (is64) {
            const int4* dw = (const int4*)(ei + 2 * (size_t)N_EDGES);
#pragma unroll
            for (int u = 0; u < 4; u++) {
                int4 v = dw[e0 / 2 + u];
                atomicAdd(&g_deg[v.x], 1);
                atomicAdd(&g_deg[v.z], 1);
            }
        } else {
            const int4* dw = (const int4*)(ei + N_EDGES);
#pragma unroll
            for (int u = 0; u < 2; u++) {
                int4 v = dw[e0 / 4 + u];
                atomicAdd(&g_deg[v.x], 1);
                atomicAdd(&g_deg[v.y], 1);
                atomicAdd(&g_deg[v.z], 1);
                atomicAdd(&g_deg[v.w], 1);
            }
        }
    }
}

// ---------------- single-kernel decoupled-lookback exclusive scan -----------
// Also zeroes g_deg after reading it (readies the buffer for the next replay).
__global__ void scan_kernel() {
    GRID_WAIT();
    const unsigned long long FLAG_A = 2ULL << 62;
    const unsigned long long FLAG_P = 3ULL << 62;
    const unsigned long long VMASK  = 0xFFFFFFFFULL;
    int b = blockIdx.x;
    int tid = threadIdx.x;
    int i = b * 256 + tid;
    int v = 0;
    if (i < N_NODES) {
        v = g_deg[i];
        g_deg[i] = 0;          // reset for next replay
    }

    int lane = tid & 31, wid = tid >> 5;
    int x = v;
#pragma unroll
    for (int o = 1; o < 32; o <<= 1) {
        int t = __shfl_up_sync(~0u, x, o);
        if (lane >= o) x += t;
    }
    __shared__ int ws[8];
    if (lane == 31) ws[wid] = x;
    __syncthreads();
    if (wid == 0 && lane < 8) {
        int w = ws[lane];
#pragma unroll
        for (int o = 1; o < 8; o <<= 1) {
            int t = __shfl_up_sync(0xffu, w, o);
            if (lane >= o) w += t;
        }
        ws[lane] = w;
    }
    __syncthreads();
    int incl = x + (wid > 0 ? ws[wid - 1] : 0);
    int total = ws[7];

    __shared__ int prefix_sh;
    if (tid == 0) {
        if (b == 0) {
            prefix_sh = 0;
            atomicExch(&g_state[0], FLAG_P | (unsigned long long)total);
            g_rowoff[N_NODES] = N_EDGES;
        } else {
            atomicExch(&g_state[b], FLAG_A | (unsigned long long)total);
            long long run = 0;
            int j = b - 1;
            while (true) {
                unsigned long long s;
                do {
                    s = *(volatile unsigned long long*)(g_state + j);
                } while ((s >> 62) < 2);
                run += (long long)(s & VMASK);
                if ((s >> 62) == 3) break;
                j--;
            }
            atomicExch(&g_state[b],
                       FLAG_P | (unsigned long long)(run + total));
            prefix_sh = (int)run;
        }
    }
    __syncthreads();
    int excl = prefix_sh + incl - v;
    if (i < N_NODES) {
        g_rowoff[i] = excl;
        g_cursor[i] = excl;
    }
}

// decode 2 edges/thread, ew = mean(edge_attr,-1), scatter packed into CSR
__global__ void fill_kernel(const int* __restrict__ ei,
                            const float* __restrict__ ea) {
    GRID_WAIT();
    int e0 = (blockIdx.x * blockDim.x + threadIdx.x) * 2;
    if (e0 >= N_EDGES) return;
    int s0, s1, d0, d1;
    if (g_is64) {
        int4 sv = *(const int4*)(ei + 2 * (size_t)e0);
        int4 dv = *(const int4*)(ei + 2 * (size_t)N_EDGES + 2 * (size_t)e0);
        s0 = sv.x; s1 = sv.z;
        d0 = dv.x; d1 = dv.z;
    } else {
        int2 sv = *(const int2*)(ei + e0);
        int2 dv = *(const int2*)(ei + N_EDGES + e0);
        s0 = sv.x; s1 = sv.y;
        d0 = dv.x; d1 = dv.y;
    }
    const float4* a4 = (const float4*)(ea + (size_t)e0 * 8);
    float4 u0 = a4[0], v0 = a4[1], u1 = a4[2], v1 = a4[3];
    float ew0 = (u0.x + u0.y + u0.z + u0.w + v0.x + v0.y + v0.z + v0.w) * 0.125f;
    float ew1 = (u1.x + u1.y + u1.z + u1.w + v1.x + v1.y + v1.z + v1.w) * 0.125f;
    int p0 = atomicAdd(&g_cursor[d0], 1);
    g_edge[p0] = make_int2(s0, __float_as_int(ew0));
    int p1 = atomicAdd(&g_cursor[d1], 1);
    g_edge[p1] = make_int2(s1, __float_as_int(ew1));
}

// ---------------- gather-aggregate (fp16 rows -> fp16 aggregate) ------------
// out_i = sum_{e: dst=i} in[src_e] * w_e ; fp32 accum, fp16 store.
// Each lane owns 8 channels: one uint4 (16B) per gathered row. 8-way edge
// unroll for MLP (8 outstanding row reads per thread).
template <int C, bool USE_W>
__global__ void gather_kernel(const __half* __restrict__ in,
                              __half* __restrict__ out) {
    GRID_WAIT();
    constexpr int L = C / 8;        // lanes per node (16 or 32)
    constexpr int G = 256 / L;      // nodes per 256-thread block
    int grp  = threadIdx.x / L;
    int lane = threadIdx.x % L;
    int node = blockIdx.x * G + grp;
    if (node >= N_NODES) return;

    int e0 = g_rowoff[node];
    int e1 = g_rowoff[node + 1];
    const uint4* in4 = (const uint4*)in;   // row stride = C/8 uint4
    float acc[8];
#pragma unroll
    for (int q = 0; q < 8; q++) acc[q] = 0.f;

    int e = e0;
    for (; e + 8 <= e1; e += 8) {
        int2 p[8];
#pragma unroll
        for (int u = 0; u < 8; u++) p[u] = __ldg(&g_edge[e + u]);
        uint4 r[8];
#pragma unroll
        for (int u = 0; u < 8; u++) r[u] = __ldg(&in4[(size_t)p[u].x * L + lane]);
#pragma unroll
        for (int u = 0; u < 8; u++) {
            float w = USE_W ? __int_as_float(p[u].y) : 1.0f;
            half2 h0 = *(half2*)&r[u].x, h1 = *(half2*)&r[u].y;
            half2 h2 = *(half2*)&r[u].z, h3 = *(half2*)&r[u].w;
            float2 f0 = __half22float2(h0), f1 = __half22float2(h1);
            float2 f2 = __half22float2(h2), f3 = __half22float2(h3);
            acc[0] = fmaf(f0.x, w, acc[0]); acc[1] = fmaf(f0.y, w, acc[1]);
            acc[2] = fmaf(f1.x, w, acc[2]); acc[3] = fmaf(f1.y, w, acc[3]);
            acc[4] = fmaf(f2.x, w, acc[4]); acc[5] = fmaf(f2.y, w, acc[5]);
            acc[6] = fmaf(f3.x, w, acc[6]); acc[7] = fmaf(f3.y, w, acc[7]);
        }
    }
    for (; e < e1; e++) {
        int2 p = __ldg(&g_edge[e]);
        float w = USE_W ? __int_as_float(p.y) : 1.0f;
        uint4 r = __ldg(&in4[(size_t)p.x * L + lane]);
        half2 h0 = *(half2*)&r.x, h1 = *(half2*)&r.y;
        half2 h2 = *(half2*)&r.z, h3 = *(half2*)&r.w;
        float2 f0 = __half22float2(h0), f1 = __half22float2(h1);
        float2 f2 = __half22float2(h2), f3 = __half22float2(h3);
        acc[0] = fmaf(f0.x, w, acc[0]); acc[1] = fmaf(f0.y, w, acc[1]);
        acc[2] = fmaf(f1.x, w, acc[2]); acc[3] = fmaf(f1.y, w, acc[3]);
        acc[4] = fmaf(f2.x, w, acc[4]); acc[5] = fmaf(f2.y, w, acc[5]);
        acc[6] = fmaf(f3.x, w, acc[6]); acc[7] = fmaf(f3.y, w, acc[7]);
    }

    half2 hh[4];
#pragma unroll
    for (int q = 0; q < 4; q++)
        hh[q] = __halves2half2(__float2half_rn(acc[2 * q]),
                               __float2half_rn(acc[2 * q + 1]));
    uint4 pH = make_uint4(h2_as_u32(hh[0]), h2_as_u32(hh[1]),
                          h2_as_u32(hh[2]), h2_as_u32(hh[3]));
    *(uint4*)(out + (size_t)node * C + lane * 8) = pH;
}

// ---------------- tensor-core GEMM (fp16, 2-stage cp.async, proven) ---------
// out[M,256] = A @ W^T + epilogue.  BM=128, BN=64, BK=32, 256 threads =
// 8 warps (4m x 2n), warp tile 32x32 = 2 m-atoms x 4 n-atoms, m16n8k16.
template <int K, bool BN_RELU, bool OUT_HALF>
__global__ void gemm_tc_kernel(const __half* __restrict__ A,
                               const __half* __restrict__ B,
                               const float* __restrict__ bias,
                               const float* __restrict__ gam,
                               const float* __restrict__ bet,
                               const float* __restrict__ mu,
                               const float* __restrict__ var,
                               void* __restrict__ out_v) {
    GRID_WAIT();
    constexpr int BM = 128, BN = 64, BK = 32;
    constexpr int PK = 20;  // row pitch in half2: conflict-free frag LDS
    constexpr int NT = K / BK;
    __shared__ __align__(16) half2 sA[2][BM][PK];
    __shared__ __align__(16) half2 sB[2][BN][PK];

    int m0 = blockIdx.x * BM;
    int n0 = blockIdx.y * BN;
    int tid = threadIdx.x;
    int lane = tid & 31;
    int g = lane >> 2;        // 0..7
    int t = lane & 3;         // 0..3
    int wid = tid >> 5;       // 0..7
    int wm = wid & 3;         // warp m index (0..3)
    int wn = wid >> 2;        // warp n index (0..1)

    int arow = tid >> 1;            // 0..127
    int akq  = (tid & 1) * 16;      // 0 or 16 (halves)
    int brow = tid >> 2;            // 0..63
    int bkq  = (tid & 3) * 8;       // 0,8,16,24 (halves)

    int arow_g   = m0 + arow;
    bool a_ok    = arow_g < N_NODES;
    int arow_cl  = a_ok ? arow_g : 0;       // clamped for address calc

    float acc[2][4][4];
#pragma unroll
    for (int i = 0; i < 2; i++)
#pragma unroll
        for (int j = 0; j < 4; j++)
#pragma unroll
            for (int c = 0; c < 4; c++) acc[i][j][c] = 0.f;

    auto load_tile = [&](int kt, int bf) {
        const __half* ap = A + (size_t)arow_cl * K + kt * BK + akq;
        unsigned dA0 = (unsigned)__cvta_generic_to_shared(&sA[bf][arow][akq / 2]);
        cp16(dA0, ap, a_ok);
        cp16(dA0 + 16, ap + 8, a_ok);
        const __half* bp = B + (size_t)(n0 + brow) * K + kt * BK + bkq;
        unsigned dB = (unsigned)__cvta_generic_to_shared(&sB[bf][brow][bkq / 2]);
        cp16(dB, bp, true);
    };

    load_tile(0, 0);
    CP_COMMIT();

#pragma unroll 1
    for (int it = 0; it < NT; it++) {
        int buf = it & 1;
        if (it + 1 < NT) {
            load_tile(it + 1, buf ^ 1);
            CP_COMMIT();
            CP_WAIT(1);
        } else {
            CP_WAIT(0);
        }
        __syncthreads();

#pragma unroll
        for (int ko = 0; ko < 2; ko++) {   // two k16 steps per BK=32 tile
            int kb = ko * 8;               // half2 offset
            unsigned ah[2][4], bh[4][2];
#pragma unroll
            for (int i = 0; i < 2; i++) {
                int rm = wm * 32 + i * 16;
                ah[i][0] = h2_as_u32(sA[buf][rm + g][kb + t]);
                ah[i][1] = h2_as_u32(sA[buf][rm + g + 8][kb + t]);
                ah[i][2] = h2_as_u32(sA[buf][rm + g][kb + t + 4]);
                ah[i][3] = h2_as_u32(sA[buf][rm + g + 8][kb + t + 4]);
            }
#pragma unroll
            for (int j = 0; j < 4; j++) {
                int cn = wn * 32 + j * 8;
                bh[j][0] = h2_as_u32(sB[buf][cn + g][kb + t]);
                bh[j][1] = h2_as_u32(sB[buf][cn + g][kb + t + 4]);
            }
#pragma unroll
            for (int i = 0; i < 2; i++)
#pragma unroll
                for (int j = 0; j < 4; j++)
                    mma_f16(acc[i][j], ah[i], bh[j]);
        }
        __syncthreads();
    }

    // ---- epilogue: +bias, optional BN(eval)+ReLU ----
#pragma unroll
    for (int j = 0; j < 4; j++) {
        int n = n0 + wn * 32 + j * 8 + 2 * t;
        float b0 = bias[n], b1 = bias[n + 1];
        float s0 = 0.f, s1 = 0.f, t0 = 0.f, t1 = 0.f;
        if (BN_RELU) {
            s0 = gam[n] * rsqrtf(var[n] + 1e-5f);
            t0 = bet[n] - mu[n] * s0;
            s1 = gam[n + 1] * rsqrtf(var[n + 1] + 1e-5f);
            t1 = bet[n + 1] - mu[n + 1] * s1;
        }
#pragma unroll
        for (int i = 0; i < 2; i++) {
            int r0 = m0 + wm * 32 + i * 16 + g;
            int r1 = r0 + 8;
            float z0 = acc[i][j][0] + b0;
            float z1 = acc[i][j][1] + b1;
            float z2 = acc[i][j][2] + b0;
            float z3 = acc[i][j][3] + b1;
            if (BN_RELU) {
                z0 = fmaxf(fmaf(z0, s0, t0), 0.f);
                z1 = fmaxf(fmaf(z1, s1, t1), 0.f);
                z2 = fmaxf(fmaf(z2, s0, t0), 0.f);
                z3 = fmaxf(fmaf(z3, s1, t1), 0.f);
            }
            if (OUT_HALF) {
                __half* oh = (__half*)out_v;
                half2 p0 = __halves2half2(__float2half_rn(z0), __float2half_rn(z1));
                half2 p1 = __halves2half2(__float2half_rn(z2), __float2half_rn(z3));
                if (r0 < N_NODES)
                    *(half2*)(oh + (size_t)r0 * C_OUT + n) = p0;
                if (r1 < N_NODES)
                    *(half2*)(oh + (size_t)r1 * C_OUT + n) = p1;
            } else {
                float* of = (float*)out_v;
                if (r0 < N_NODES)
                    *(float2*)(of + (size_t)r0 * C_OUT + n) = make_float2(z0, z1);
                if (r1 < N_NODES)
                    *(float2*)(of + (size_t)r1 * C_OUT + n) = make_float2(z2, z3);
            }
        }
    }
}

// ---------------- PDL launch helper -----------------------------------------
template <typename F, typename... Args>
static inline void launch_pdl(F* kern, dim3 grid, dim3 block, Args... args) {
    cudaLaunchConfig_t cfg = {};
    cfg.gridDim = grid;
    cfg.blockDim = block;
    cudaLaunchAttribute attr[1];
    attr[0].id = cudaLaunchAttributeProgrammaticStreamSerialization;
    attr[0].val.programmaticStreamSerializationAllowed = 1;
    cfg.attrs = attr;
    cfg.numAttrs = 1;
    cudaLaunchKernelEx(&cfg, kern, args...);
}

// ---------------- launch ----------------------------------------------------
extern "C" void kernel_launch(void* const* d_in, const int* in_sizes, int n_in,
                              void* d_out, int out_size) {
    const float* x   = (const float*)d_in[0];
    const int*   ei  = (const int*)d_in[1];
    const float* ea  = (const float*)d_in[2];
    const float* W1  = (const float*)d_in[3];
    const float* b1  = (const float*)d_in[4];
    const float* g1  = (const float*)d_in[5];
    const float* be1 = (const float*)d_in[6];
    const float* m1  = (const float*)d_in[7];
    const float* v1  = (const float*)d_in[8];
    const float* W2  = (const float*)d_in[9];
    const float* b2  = (const float*)d_in[10];
    const float* g2  = (const float*)d_in[11];
    const float* be2 = (const float*)d_in[12];
    const float* m2  = (const float*)d_in[13];
    const float* v2  = (const float*)d_in[14];
    const float* W3  = (const float*)d_in[15];
    const float* b3  = (const float*)d_in[16];

    void *p_agg, *p_hf, *p_xh, *p_WH;
    cudaGetSymbolAddress(&p_agg, g_agg);
    cudaGetSymbolAddress(&p_hf, g_hf);
    cudaGetSymbolAddress(&p_xh, g_xh);
    cudaGetSymbolAddress(&p_WH, g_WH);
    __half* agg = (__half*)p_agg;
    __half* hf  = (__half*)p_hf;
    __half* xh  = (__half*)p_xh;
    __half* WH  = (__half*)p_WH;
    const int offW2 = W1_N;
    const int offW3 = W1_N + W2_N;

    // ---- CSR build + conversions (once) ----
    // g_deg starts zeroed (static storage) and scan_kernel re-zeroes it each
    // replay; g_state is re-zeroed in prep_kernel block 0.
    prep_kernel<<<PREP_BLOCKS, 256>>>(W1, W2, W3, x, ei);
    launch_pdl(scan_kernel, dim3(SCAN_BLOCKS), dim3(256));
    launch_pdl(fill_kernel, dim3((N_EDGES / 2 + 255) / 256), dim3(256), ei, ea);

    dim3 ggrid((N_NODES + 127) / 128, 4);  // 391 x 4, BM=128 BN=64

    // ---- layer 1: gather x_fp16 (C=128), GEMM K=128 + BN1 + ReLU -> fp16 h --
    launch_pdl(gather_kernel<128, true>, dim3((N_NODES + 15) / 16), dim3(256),
               (const __half*)xh, (__half*)agg);
    launch_pdl(gemm_tc_kernel<128, true, true>, ggrid, dim3(256),
               (const __half*)agg, (const __half*)WH,
               b1, g1, be1, m1, v1, (void*)hf);

    // ---- layer 2: gather h_fp16 (C=256), GEMM K=256 + BN2 + ReLU -> fp16 h --
    launch_pdl(gather_kernel<256, true>, dim3((N_NODES + 7) / 8), dim3(256),
               (const __half*)hf, (__half*)agg);
    launch_pdl(gemm_tc_kernel<256, true, true>, ggrid, dim3(256),
               (const __half*)agg, (const __half*)(WH + offW2),
               b2, g2, be2, m2, v2, (void*)hf);

    // ---- layer 3: gather h_fp16 (C=256, no weight), GEMM + bias -> fp32 out -
    launch_pdl(gather_kernel<256, false>, dim3((N_NODES + 7) / 8), dim3(256),
               (const __half*)hf, (__half*)agg);
    launch_pdl(gemm_tc_kernel<256, false, false>, ggrid, dim3(256),
               (const __half*)agg, (const __half*)(WH + offW3),
               b3, (const float*)nullptr, (const float*)nullptr,
               (const float*)nullptr, (const float*)nullptr, d_out);
}